// round 5
// baseline (speedup 1.0000x reference)
#include <cuda_runtime.h>
#include <cuda_bf16.h>
#include <math.h>

#define EMBD   256
#define HEADS  16
#define DHEAD  16
#define BATCH  64
#define MROWS  128
#define JJOBS  512
#define TTOK   513
#define OUT_PER_B (MROWS * TTOK)   // 65664

typedef unsigned long long ull;

__device__ float g_Q [BATCH * MROWS * EMBD];
__device__ float g_K [BATCH * TTOK  * EMBD];
__device__ float g_V [BATCH * TTOK  * EMBD];
__device__ float g_O [BATCH * MROWS * EMBD];
__device__ float g_MH[BATCH * MROWS * EMBD];
__device__ float g_SUM[BATCH];

// ---------------- packed f32x2 helpers (sm_103a) ----------------
__device__ __forceinline__ ull fma2(ull a, ull b, ull c) {
    ull d; asm("fma.rn.f32x2 %0, %1, %2, %3;" : "=l"(d) : "l"(a), "l"(b), "l"(c));
    return d;
}
__device__ __forceinline__ ull mul2(ull a, ull b) {
    ull d; asm("mul.rn.f32x2 %0, %1, %2;" : "=l"(d) : "l"(a), "l"(b));
    return d;
}
__device__ __forceinline__ ull bcast2(float x) {
    ull d; asm("mov.b64 %0, {%1, %2};" : "=l"(d) : "f"(x), "f"(x));
    return d;
}
__device__ __forceinline__ float2 unpack2(ull v) {
    float2 f; asm("mov.b64 {%0, %1}, %2;" : "=f"(f.x), "=f"(f.y) : "l"(v));
    return f;
}

// exact-enough tanh: (1 - 2/(e^{2x}+1)); MUFU ex2 + approx rcp, err ~1e-6
__device__ __forceinline__ float tanh_fast(float x) {
    const float e = __expf(2.0f * x);
    return 1.0f - __fdividef(2.0f, e + 1.0f);
}

__device__ __forceinline__ const float* jobs_row(const float* __restrict__ jobs,
                                                 const float* __restrict__ skip,
                                                 int b, int t) {
    return (t == 0) ? skip : jobs + ((long)b * JJOBS + (t - 1)) * EMBD;
}

// =================== tiles ===================
#define BM 128
#define BN 128
#define BK 16
#define ASTRIDE (BM + 4)

#define GEMM_MICRO(cur)                                                        \
    _Pragma("unroll")                                                          \
    for (int kk = 0; kk < BK; kk++) {                                          \
        float4 a0 = *(const float4*)&As[cur][kk][ty * 4];                      \
        float4 a1 = *(const float4*)&As[cur][kk][64 + ty * 4];                 \
        ulonglong2 p0 = *(const ulonglong2*)&Bs[cur][kk][tx * 4];              \
        ulonglong2 p1 = *(const ulonglong2*)&Bs[cur][kk][64 + tx * 4];         \
        ull B2[4] = {p0.x, p0.y, p1.x, p1.y};                                  \
        float a[8] = {a0.x,a0.y,a0.z,a0.w,a1.x,a1.y,a1.z,a1.w};                \
        _Pragma("unroll")                                                      \
        for (int i = 0; i < 8; i++) {                                          \
            const ull ai = bcast2(a[i]);                                       \
            _Pragma("unroll")                                                  \
            for (int j = 0; j < 4; j++)                                        \
                acc2[i][j] = fma2(ai, B2[j], acc2[i][j]);                      \
        }                                                                      \
    }

// =================== merged projection kernel (Q, K, V) ====================
__global__ void __launch_bounds__(256, 2)
proj_kernel(const float* __restrict__ jobs, const float* __restrict__ skip,
            const float* __restrict__ machine,
            const float* __restrict__ Wk, const float* __restrict__ Wv,
            const float* __restrict__ Wq,
            float* __restrict__ Kout, float* __restrict__ Vout,
            float* __restrict__ Qout, float* __restrict__ sums)
{
    __shared__ float As[2][BK][ASTRIDE];
    __shared__ float Bs[2][BK][BN];

    const int z = blockIdx.z;
    const int row0 = blockIdx.y * BM;
    const int nrows = (z == 2) ? (BATCH * MROWS) : (BATCH * TTOK);

    // fold sums-zeroing into this launch (completes before score2 runs)
    if (z == 2 && blockIdx.x == 0 && blockIdx.y == 0 && threadIdx.x < BATCH)
        sums[threadIdx.x] = 0.0f;
    if (row0 >= nrows) return;

    const float* W = (z == 0) ? Wk : (z == 1) ? Wv : Wq;
    float*       C = (z == 0) ? Kout : (z == 1) ? Vout : Qout;

    const int tid  = threadIdx.x;
    const int col0 = blockIdx.x * BN;

    const int a_row = tid >> 1;
    const int a_k   = (tid & 1) * 8;
    const int b_k   = tid >> 4;
    const int b_n   = (tid & 15) * 8;
    const int tx = tid & 15;
    const int ty = tid >> 4;

    const float* xrow;
    {
        int grow = row0 + a_row;
        if (grow > nrows - 1) grow = nrows - 1;
        if (z == 2) {
            xrow = machine + (long)grow * EMBD;
        } else {
            const int b = grow / TTOK;
            const int t = grow - b * TTOK;
            xrow = jobs_row(jobs, skip, b, t);
        }
    }
    const float* wptr = W + (long)b_k * EMBD + col0 + b_n;

    float4 av0, av1, bv0, bv1;
    av0 = *(const float4*)(xrow + a_k);
    av1 = *(const float4*)(xrow + a_k + 4);
    bv0 = *(const float4*)(wptr);
    bv1 = *(const float4*)(wptr + 4);
    As[0][a_k+0][a_row]=av0.x; As[0][a_k+1][a_row]=av0.y;
    As[0][a_k+2][a_row]=av0.z; As[0][a_k+3][a_row]=av0.w;
    As[0][a_k+4][a_row]=av1.x; As[0][a_k+5][a_row]=av1.y;
    As[0][a_k+6][a_row]=av1.z; As[0][a_k+7][a_row]=av1.w;
    *(float4*)&Bs[0][b_k][b_n]     = bv0;
    *(float4*)&Bs[0][b_k][b_n + 4] = bv1;
    __syncthreads();

    ull acc2[8][4] = {};

    #pragma unroll 1
    for (int ks = 0; ks < EMBD / BK; ks++) {
        const int cur = ks & 1;
        const bool has_next = (ks < EMBD / BK - 1);
        if (has_next) {
            const int k0 = (ks + 1) * BK;
            av0 = *(const float4*)(xrow + k0 + a_k);
            av1 = *(const float4*)(xrow + k0 + a_k + 4);
            bv0 = *(const float4*)(wptr + (long)k0 * EMBD);
            bv1 = *(const float4*)(wptr + (long)k0 * EMBD + 4);
        }
        GEMM_MICRO(cur)
        if (has_next) {
            const int nxt = 1 - cur;
            As[nxt][a_k+0][a_row]=av0.x; As[nxt][a_k+1][a_row]=av0.y;
            As[nxt][a_k+2][a_row]=av0.z; As[nxt][a_k+3][a_row]=av0.w;
            As[nxt][a_k+4][a_row]=av1.x; As[nxt][a_k+5][a_row]=av1.y;
            As[nxt][a_k+6][a_row]=av1.z; As[nxt][a_k+7][a_row]=av1.w;
            *(float4*)&Bs[nxt][b_k][b_n]     = bv0;
            *(float4*)&Bs[nxt][b_k][b_n + 4] = bv1;
        }
        __syncthreads();
    }

    #pragma unroll
    for (int half = 0; half < 2; half++) {
        #pragma unroll
        for (int i = 0; i < 4; i++) {
            const int r = row0 + half * 64 + ty * 4 + i;
            if (r < nrows) {
                const int ai = half * 4 + i;
                float2 c0 = unpack2(acc2[ai][0]);
                float2 c1 = unpack2(acc2[ai][1]);
                float2 c2 = unpack2(acc2[ai][2]);
                float2 c3 = unpack2(acc2[ai][3]);
                float4 o0 = make_float4(c0.x, c0.y, c1.x, c1.y);
                float4 o1 = make_float4(c2.x, c2.y, c3.x, c3.y);
                *(float4*)(C + (long)r * EMBD + col0 + tx * 4)      = o0;
                *(float4*)(C + (long)r * EMBD + col0 + 64 + tx * 4) = o1;
            }
        }
    }
}

// =================== Wc projection (+bias), 64x128 tiles ====================
#define WBM 64
__global__ void __launch_bounds__(256)
wc_kernel(const float* __restrict__ X, const float* __restrict__ W,
          const float* __restrict__ bias, float* __restrict__ C)
{
    __shared__ float As[2][BK][WBM + 4];
    __shared__ float Bs[2][BK][BN];

    const int tid  = threadIdx.x;
    const int row0 = blockIdx.y * WBM;
    const int col0 = blockIdx.x * BN;

    // A loader: one float4 per thread: row = tid>>2 (0..63), k = (tid&3)*4
    const int a_row = tid >> 2;
    const int a_k   = (tid & 3) * 4;
    const int b_k   = tid >> 4;
    const int b_n   = (tid & 15) * 8;
    const int tx = tid & 15;
    const int ty = tid >> 4;           // rows ty*4..ty*4+3

    const float* xrow = X + (long)(row0 + a_row) * EMBD;
    const float* wptr = W + (long)b_k * EMBD + col0 + b_n;

    float4 av, bv0, bv1;
    av  = *(const float4*)(xrow + a_k);
    bv0 = *(const float4*)(wptr);
    bv1 = *(const float4*)(wptr + 4);
    As[0][a_k+0][a_row]=av.x; As[0][a_k+1][a_row]=av.y;
    As[0][a_k+2][a_row]=av.z; As[0][a_k+3][a_row]=av.w;
    *(float4*)&Bs[0][b_k][b_n]     = bv0;
    *(float4*)&Bs[0][b_k][b_n + 4] = bv1;
    __syncthreads();

    ull acc2[4][4] = {};

    #pragma unroll 1
    for (int ks = 0; ks < EMBD / BK; ks++) {
        const int cur = ks & 1;
        const bool has_next = (ks < EMBD / BK - 1);
        if (has_next) {
            const int k0 = (ks + 1) * BK;
            av  = *(const float4*)(xrow + k0 + a_k);
            bv0 = *(const float4*)(wptr + (long)k0 * EMBD);
            bv1 = *(const float4*)(wptr + (long)k0 * EMBD + 4);
        }
        #pragma unroll
        for (int kk = 0; kk < BK; kk++) {
            float4 a0 = *(const float4*)&As[cur][kk][ty * 4];
            ulonglong2 p0 = *(const ulonglong2*)&Bs[cur][kk][tx * 4];
            ulonglong2 p1 = *(const ulonglong2*)&Bs[cur][kk][64 + tx * 4];
            ull B2[4] = {p0.x, p0.y, p1.x, p1.y};
            float a[4] = {a0.x, a0.y, a0.z, a0.w};
            #pragma unroll
            for (int i = 0; i < 4; i++) {
                const ull ai = bcast2(a[i]);
                #pragma unroll
                for (int j = 0; j < 4; j++)
                    acc2[i][j] = fma2(ai, B2[j], acc2[i][j]);
            }
        }
        if (has_next) {
            const int nxt = 1 - cur;
            As[nxt][a_k+0][a_row]=av.x; As[nxt][a_k+1][a_row]=av.y;
            As[nxt][a_k+2][a_row]=av.z; As[nxt][a_k+3][a_row]=av.w;
            *(float4*)&Bs[nxt][b_k][b_n]     = bv0;
            *(float4*)&Bs[nxt][b_k][b_n + 4] = bv1;
        }
        __syncthreads();
    }

    float4 bb0 = *(const float4*)(bias + col0 + tx * 4);
    float4 bb1 = *(const float4*)(bias + col0 + 64 + tx * 4);

    #pragma unroll
    for (int i = 0; i < 4; i++) {
        const int r = row0 + ty * 4 + i;
        float2 c0 = unpack2(acc2[i][0]);
        float2 c1 = unpack2(acc2[i][1]);
        float2 c2 = unpack2(acc2[i][2]);
        float2 c3 = unpack2(acc2[i][3]);
        float4 o0 = make_float4(c0.x+bb0.x, c0.y+bb0.y, c1.x+bb0.z, c1.y+bb0.w);
        float4 o1 = make_float4(c2.x+bb1.x, c2.y+bb1.y, c3.x+bb1.z, c3.y+bb1.w);
        *(float4*)(C + (long)r * EMBD + col0 + tx * 4)      = o0;
        *(float4*)(C + (long)r * EMBD + col0 + 64 + tx * 4) = o1;
    }
}

// =================== attention: no online max (scores bounded) =============
__global__ void __launch_bounds__(128)
attn_kernel(const float* __restrict__ Q, const float* __restrict__ K,
            const float* __restrict__ V, float* __restrict__ O)
{
    __shared__ float Ks[128][DHEAD];
    __shared__ float Vs[128][DHEAD];

    const int h = blockIdx.x;
    const int b = blockIdx.y;
    const int m = threadIdx.x;

    ull q2[8];
    {
        const float* qp = Q + ((long)b * MROWS + m) * EMBD + h * DHEAD;
        #pragma unroll
        for (int p = 0; p < 4; p++) {
            ulonglong2 v = *(const ulonglong2*)(qp + p * 4);
            q2[2*p] = v.x; q2[2*p+1] = v.y;
        }
    }

    float l = 0.0f;
    ull acc2[8] = {};

    #pragma unroll 1
    for (int c = 0; c < 4; c++) {
        const int t0 = c * 128;
        __syncthreads();
        #pragma unroll
        for (int j = 0; j < 4; j++) {
            const int idx = m + j * 128;
            const int rr = idx >> 2, cc = (idx & 3) * 4;
            const long base = ((long)b * TTOK + t0 + rr) * EMBD + h * DHEAD + cc;
            *(float4*)&Ks[rr][cc] = *(const float4*)(K + base);
            *(float4*)&Vs[rr][cc] = *(const float4*)(V + base);
        }
        __syncthreads();

        #pragma unroll 1
        for (int tt = 0; tt < 128; tt += 8) {
            float s[8];
            #pragma unroll
            for (int j = 0; j < 8; j++) {
                const ulonglong2* kp = (const ulonglong2*)Ks[tt + j];
                ulonglong2 k0 = kp[0], k1 = kp[1];
                ull d2 = mul2(q2[0], k0.x);
                d2 = fma2(q2[1], k0.y, d2);
                d2 = fma2(q2[2], k1.x, d2);
                d2 = fma2(q2[3], k1.y, d2);
                ulonglong2 k2v = kp[2], k3 = kp[3];
                d2 = fma2(q2[4], k2v.x, d2);
                d2 = fma2(q2[5], k2v.y, d2);
                d2 = fma2(q2[6], k3.x, d2);
                d2 = fma2(q2[7], k3.y, d2);
                float2 f = unpack2(d2);
                s[j] = (f.x + f.y) * 0.25f;
            }
            float p[8];
            #pragma unroll
            for (int j = 0; j < 8; j++) { p[j] = __expf(s[j]); l += p[j]; }
            #pragma unroll
            for (int j = 0; j < 8; j++) {
                const ull pb = bcast2(p[j]);
                const ulonglong2* vp = (const ulonglong2*)Vs[tt + j];
                ulonglong2 v0 = vp[0], v1 = vp[1];
                acc2[0] = fma2(pb, v0.x, acc2[0]);
                acc2[1] = fma2(pb, v0.y, acc2[1]);
                acc2[2] = fma2(pb, v1.x, acc2[2]);
                acc2[3] = fma2(pb, v1.y, acc2[3]);
                ulonglong2 v2v = vp[2], v3 = vp[3];
                acc2[4] = fma2(pb, v2v.x, acc2[4]);
                acc2[5] = fma2(pb, v2v.y, acc2[5]);
                acc2[6] = fma2(pb, v3.x, acc2[6]);
                acc2[7] = fma2(pb, v3.y, acc2[7]);
            }
        }
    }

    // tail token t = 512 (from global)
    {
        const long base = ((long)b * TTOK + 512) * EMBD + h * DHEAD;
        const ulonglong2* kp = (const ulonglong2*)(K + base);
        ulonglong2 k0 = kp[0], k1 = kp[1], k2v = kp[2], k3 = kp[3];
        ull d2 = mul2(q2[0], k0.x);
        d2 = fma2(q2[1], k0.y, d2);
        d2 = fma2(q2[2], k1.x, d2);
        d2 = fma2(q2[3], k1.y, d2);
        d2 = fma2(q2[4], k2v.x, d2);
        d2 = fma2(q2[5], k2v.y, d2);
        d2 = fma2(q2[6], k3.x, d2);
        d2 = fma2(q2[7], k3.y, d2);
        float2 f = unpack2(d2);
        const float pw = __expf((f.x + f.y) * 0.25f);
        l += pw;
        const ull pb = bcast2(pw);
        const ulonglong2* vp = (const ulonglong2*)(V + base);
        ulonglong2 v0 = vp[0], v1 = vp[1], v2v = vp[2], v3 = vp[3];
        acc2[0] = fma2(pb, v0.x,  acc2[0]);
        acc2[1] = fma2(pb, v0.y,  acc2[1]);
        acc2[2] = fma2(pb, v1.x,  acc2[2]);
        acc2[3] = fma2(pb, v1.y,  acc2[3]);
        acc2[4] = fma2(pb, v2v.x, acc2[4]);
        acc2[5] = fma2(pb, v2v.y, acc2[5]);
        acc2[6] = fma2(pb, v3.x,  acc2[6]);
        acc2[7] = fma2(pb, v3.y,  acc2[7]);
    }

    const float inv = 1.0f / l;
    float* op = O + ((long)b * MROWS + m) * EMBD + h * DHEAD;
    #pragma unroll
    for (int p = 0; p < 4; p++) {
        float2 x0 = unpack2(acc2[2*p]);
        float2 x1 = unpack2(acc2[2*p+1]);
        float4 o = make_float4(x0.x * inv, x0.y * inv, x1.x * inv, x1.y * inv);
        *(float4*)(op + p * 4) = o;
    }
}

// =================== score2: 128x128 tiles + fast tanh/exp epilogue ========
__global__ void __launch_bounds__(256, 2)
score2_kernel(const float* __restrict__ MH, const float* __restrict__ jobs,
              const float* __restrict__ skip, const float* __restrict__ mask,
              float* __restrict__ out, float* __restrict__ sums)
{
    __shared__ float As[2][BK][ASTRIDE];
    __shared__ float Bs[2][BK][BN + 4];
    __shared__ float red[256];

    const int tid  = threadIdx.x;
    const int b    = blockIdx.z;
    const int col0 = blockIdx.x * BN;

    const int a_row = tid >> 1;
    const int a_k   = (tid & 1) * 8;
    const int tx = tid & 15;
    const int ty = tid >> 4;

    const float* arow = MH + ((long)b * MROWS + a_row) * EMBD;

    const int t_l = tid >> 1;
    const int t_g = col0 + t_l;
    const float* brow = (t_g < TTOK) ? jobs_row(jobs, skip, b, t_g) : nullptr;

    float4 av0, av1, bv0, bv1;
    av0 = *(const float4*)(arow + a_k);
    av1 = *(const float4*)(arow + a_k + 4);
    bv0 = bv1 = make_float4(0.f,0.f,0.f,0.f);
    if (brow) { bv0 = *(const float4*)(brow + a_k); bv1 = *(const float4*)(brow + a_k + 4); }
    As[0][a_k+0][a_row]=av0.x; As[0][a_k+1][a_row]=av0.y;
    As[0][a_k+2][a_row]=av0.z; As[0][a_k+3][a_row]=av0.w;
    As[0][a_k+4][a_row]=av1.x; As[0][a_k+5][a_row]=av1.y;
    As[0][a_k+6][a_row]=av1.z; As[0][a_k+7][a_row]=av1.w;
    Bs[0][a_k+0][t_l]=bv0.x; Bs[0][a_k+1][t_l]=bv0.y;
    Bs[0][a_k+2][t_l]=bv0.z; Bs[0][a_k+3][t_l]=bv0.w;
    Bs[0][a_k+4][t_l]=bv1.x; Bs[0][a_k+5][t_l]=bv1.y;
    Bs[0][a_k+6][t_l]=bv1.z; Bs[0][a_k+7][t_l]=bv1.w;
    __syncthreads();

    ull acc2[8][4] = {};

    #pragma unroll 1
    for (int ks = 0; ks < EMBD / BK; ks++) {
        const int cur = ks & 1;
        const bool has_next = (ks < EMBD / BK - 1);
        if (has_next) {
            const int k0 = (ks + 1) * BK;
            av0 = *(const float4*)(arow + k0 + a_k);
            av1 = *(const float4*)(arow + k0 + a_k + 4);
            if (brow) {
                bv0 = *(const float4*)(brow + k0 + a_k);
                bv1 = *(const float4*)(brow + k0 + a_k + 4);
            }
        }
        GEMM_MICRO(cur)
        if (has_next) {
            const int nxt = 1 - cur;
            As[nxt][a_k+0][a_row]=av0.x; As[nxt][a_k+1][a_row]=av0.y;
            As[nxt][a_k+2][a_row]=av0.z; As[nxt][a_k+3][a_row]=av0.w;
            As[nxt][a_k+4][a_row]=av1.x; As[nxt][a_k+5][a_row]=av1.y;
            As[nxt][a_k+6][a_row]=av1.z; As[nxt][a_k+7][a_row]=av1.w;
            Bs[nxt][a_k+0][t_l]=bv0.x; Bs[nxt][a_k+1][t_l]=bv0.y;
            Bs[nxt][a_k+2][t_l]=bv0.z; Bs[nxt][a_k+3][t_l]=bv0.w;
            Bs[nxt][a_k+4][t_l]=bv1.x; Bs[nxt][a_k+5][t_l]=bv1.y;
            Bs[nxt][a_k+6][t_l]=bv1.z; Bs[nxt][a_k+7][t_l]=bv1.w;
        }
        __syncthreads();
    }

    float lsum = 0.0f;
    #pragma unroll
    for (int half = 0; half < 2; half++) {
        #pragma unroll
        for (int i = 0; i < 4; i++) {
            const int m = half * 64 + ty * 4 + i;
            const int ai = half * 4 + i;
            #pragma unroll
            for (int jh = 0; jh < 2; jh++) {
                #pragma unroll
                for (int jj = 0; jj < 2; jj++) {
                    float2 v = unpack2(acc2[ai][jh * 2 + jj]);
                    const int t = col0 + jh * 64 + tx * 4 + jj * 2;
                    if (t < TTOK) {
                        const long li = (long)b * OUT_PER_B + (long)m * TTOK + t;
                        const float lg = 10.0f * tanh_fast(v.x * 0.0625f) + mask[li];
                        const float y = __expf(lg);
                        out[li] = y;
                        lsum += y;
                    }
                    if (t + 1 < TTOK) {
                        const long li = (long)b * OUT_PER_B + (long)m * TTOK + t + 1;
                        const float lg = 10.0f * tanh_fast(v.y * 0.0625f) + mask[li];
                        const float y = __expf(lg);
                        out[li] = y;
                        lsum += y;
                    }
                }
            }
        }
    }

    red[tid] = lsum;
    __syncthreads();
    #pragma unroll
    for (int s = 128; s > 0; s >>= 1) {
        if (tid < s) red[tid] += red[tid + s];
        __syncthreads();
    }
    if (tid == 0) atomicAdd(&sums[b], red[0]);
}

// =================== normalize: grid (chunks, batch) =======================
__global__ void __launch_bounds__(256)
norm_kernel(float4* __restrict__ out, const float* __restrict__ sums)
{
    const int b = blockIdx.y;
    const long per_b4 = OUT_PER_B / 4;
    const long idx = (long)blockIdx.x * blockDim.x + threadIdx.x;
    if (idx < per_b4) {
        const float inv = 1.0f / sums[b];
        float4 v = out[(long)b * per_b4 + idx];
        v.x *= inv; v.y *= inv; v.z *= inv; v.w *= inv;
        out[(long)b * per_b4 + idx] = v;
    }
}

// =================== launch ===================
extern "C" void kernel_launch(void* const* d_in, const int* in_sizes, int n_in,
                              void* d_out, int out_size)
{
    const float* machine = (const float*)d_in[0];
    const float* jobs    = (const float*)d_in[1];
    const float* mask    = (const float*)d_in[2];
    const float* Wq3     = (const float*)d_in[3];
    const float* Wk      = (const float*)d_in[4];
    const float* Wv      = (const float*)d_in[5];
    const float* Wc      = (const float*)d_in[6];
    const float* bc      = (const float*)d_in[7];
    const float* skip    = (const float*)d_in[8];
    float* out = (float*)d_out;

    float *Qp, *Kp, *Vp, *Op, *MHp, *Sp;
    cudaGetSymbolAddress((void**)&Qp,  g_Q);
    cudaGetSymbolAddress((void**)&Kp,  g_K);
    cudaGetSymbolAddress((void**)&Vp,  g_V);
    cudaGetSymbolAddress((void**)&Op,  g_O);
    cudaGetSymbolAddress((void**)&MHp, g_MH);
    cudaGetSymbolAddress((void**)&Sp,  g_SUM);

    // Q + K + V projections in one launch (also zeroes sums)
    const int kv_tiles = (BATCH * TTOK + BM - 1) / BM;   // 257
    proj_kernel<<<dim3(EMBD / BN, kv_tiles, 3), 256>>>(
        jobs, skip, machine, Wk, Wv, Wq3, Kp, Vp, Qp, Sp);

    attn_kernel<<<dim3(HEADS, BATCH), 128>>>(Qp, Kp, Vp, Op);

    wc_kernel<<<dim3(EMBD / BN, (BATCH * MROWS) / WBM), 256>>>(Op, Wc, bc, MHp);

    score2_kernel<<<dim3((TTOK + BN - 1) / BN, 1, BATCH), 256>>>(
        MHp, jobs, skip, mask, out, Sp);

    const int per_b4 = OUT_PER_B / 4;
    norm_kernel<<<dim3((per_b4 + 255) / 256, BATCH), 256>>>((float4*)out, Sp);
}

// round 7
// speedup vs baseline: 1.1558x; 1.1558x over previous
#include <cuda_runtime.h>
#include <cuda_bf16.h>
#include <math.h>

#define EMBD   256
#define HEADS  16
#define DHEAD  16
#define BATCH  64
#define MROWS  128
#define JJOBS  512
#define TTOK   513
#define OUT_PER_B (MROWS * TTOK)   // 65664

typedef unsigned long long ull;

__device__ float g_Q [BATCH * MROWS * EMBD];
__device__ float g_K [BATCH * TTOK  * EMBD];
__device__ float g_V [BATCH * TTOK  * EMBD];
__device__ float g_O [BATCH * MROWS * EMBD];
__device__ float g_MH[BATCH * MROWS * EMBD];
__device__ float g_SUM[BATCH];

// ---------------- packed f32x2 helpers (sm_103a) ----------------
__device__ __forceinline__ ull fma2(ull a, ull b, ull c) {
    ull d; asm("fma.rn.f32x2 %0, %1, %2, %3;" : "=l"(d) : "l"(a), "l"(b), "l"(c));
    return d;
}
__device__ __forceinline__ ull mul2(ull a, ull b) {
    ull d; asm("mul.rn.f32x2 %0, %1, %2;" : "=l"(d) : "l"(a), "l"(b));
    return d;
}
__device__ __forceinline__ ull bcast2(float x) {
    ull d; asm("mov.b64 %0, {%1, %2};" : "=l"(d) : "f"(x), "f"(x));
    return d;
}
__device__ __forceinline__ float2 unpack2(ull v) {
    float2 f; asm("mov.b64 {%0, %1}, %2;" : "=f"(f.x), "=f"(f.y) : "l"(v));
    return f;
}

// exact-enough tanh: (1 - 2/(e^{2x}+1)); err ~1e-6
__device__ __forceinline__ float tanh_fast(float x) {
    const float e = __expf(2.0f * x);
    return 1.0f - __fdividef(2.0f, e + 1.0f);
}

__device__ __forceinline__ const float* jobs_row(const float* __restrict__ jobs,
                                                 const float* __restrict__ skip,
                                                 int b, int t) {
    return (t == 0) ? skip : jobs + ((long)b * JJOBS + (t - 1)) * EMBD;
}

// =================== tiles ===================
#define BM 128
#define BN 128
#define BK 16
#define ASTRIDE (BM + 4)

#define GEMM_MICRO(cur)                                                        \
    _Pragma("unroll")                                                          \
    for (int kk = 0; kk < BK; kk++) {                                          \
        float4 a0 = *(const float4*)&As[cur][kk][ty * 4];                      \
        float4 a1 = *(const float4*)&As[cur][kk][64 + ty * 4];                 \
        ulonglong2 p0 = *(const ulonglong2*)&Bs[cur][kk][tx * 4];              \
        ulonglong2 p1 = *(const ulonglong2*)&Bs[cur][kk][64 + tx * 4];         \
        ull B2[4] = {p0.x, p0.y, p1.x, p1.y};                                  \
        float a[8] = {a0.x,a0.y,a0.z,a0.w,a1.x,a1.y,a1.z,a1.w};                \
        _Pragma("unroll")                                                      \
        for (int i = 0; i < 8; i++) {                                          \
            const ull ai = bcast2(a[i]);                                       \
            _Pragma("unroll")                                                  \
            for (int j = 0; j < 4; j++)                                        \
                acc2[i][j] = fma2(ai, B2[j], acc2[i][j]);                      \
        }                                                                      \
    }

// =================== merged projection kernel (Q, K, V) ====================
__global__ void __launch_bounds__(256, 2)
proj_kernel(const float* __restrict__ jobs, const float* __restrict__ skip,
            const float* __restrict__ machine,
            const float* __restrict__ Wk, const float* __restrict__ Wv,
            const float* __restrict__ Wq,
            float* __restrict__ Kout, float* __restrict__ Vout,
            float* __restrict__ Qout, float* __restrict__ sums)
{
    __shared__ float As[2][BK][ASTRIDE];
    __shared__ float Bs[2][BK][BN];

    const int z = blockIdx.z;
    const int row0 = blockIdx.y * BM;
    const int nrows = (z == 2) ? (BATCH * MROWS) : (BATCH * TTOK);

    if (z == 2 && blockIdx.x == 0 && blockIdx.y == 0 && threadIdx.x < BATCH)
        sums[threadIdx.x] = 0.0f;
    if (row0 >= nrows) return;

    const float* W = (z == 0) ? Wk : (z == 1) ? Wv : Wq;
    float*       C = (z == 0) ? Kout : (z == 1) ? Vout : Qout;

    const int tid  = threadIdx.x;
    const int col0 = blockIdx.x * BN;

    const int a_row = tid >> 1;
    const int a_k   = (tid & 1) * 8;
    const int b_k   = tid >> 4;
    const int b_n   = (tid & 15) * 8;
    const int tx = tid & 15;
    const int ty = tid >> 4;

    const float* xrow;
    {
        int grow = row0 + a_row;
        if (grow > nrows - 1) grow = nrows - 1;
        if (z == 2) {
            xrow = machine + (long)grow * EMBD;
        } else {
            const int b = grow / TTOK;
            const int t = grow - b * TTOK;
            xrow = jobs_row(jobs, skip, b, t);
        }
    }
    const float* wptr = W + (long)b_k * EMBD + col0 + b_n;

    float4 av0, av1, bv0, bv1;
    av0 = *(const float4*)(xrow + a_k);
    av1 = *(const float4*)(xrow + a_k + 4);
    bv0 = *(const float4*)(wptr);
    bv1 = *(const float4*)(wptr + 4);
    As[0][a_k+0][a_row]=av0.x; As[0][a_k+1][a_row]=av0.y;
    As[0][a_k+2][a_row]=av0.z; As[0][a_k+3][a_row]=av0.w;
    As[0][a_k+4][a_row]=av1.x; As[0][a_k+5][a_row]=av1.y;
    As[0][a_k+6][a_row]=av1.z; As[0][a_k+7][a_row]=av1.w;
    *(float4*)&Bs[0][b_k][b_n]     = bv0;
    *(float4*)&Bs[0][b_k][b_n + 4] = bv1;
    __syncthreads();

    ull acc2[8][4] = {};

    #pragma unroll 1
    for (int ks = 0; ks < EMBD / BK; ks++) {
        const int cur = ks & 1;
        const bool has_next = (ks < EMBD / BK - 1);
        if (has_next) {
            const int k0 = (ks + 1) * BK;
            av0 = *(const float4*)(xrow + k0 + a_k);
            av1 = *(const float4*)(xrow + k0 + a_k + 4);
            bv0 = *(const float4*)(wptr + (long)k0 * EMBD);
            bv1 = *(const float4*)(wptr + (long)k0 * EMBD + 4);
        }
        GEMM_MICRO(cur)
        if (has_next) {
            const int nxt = 1 - cur;
            As[nxt][a_k+0][a_row]=av0.x; As[nxt][a_k+1][a_row]=av0.y;
            As[nxt][a_k+2][a_row]=av0.z; As[nxt][a_k+3][a_row]=av0.w;
            As[nxt][a_k+4][a_row]=av1.x; As[nxt][a_k+5][a_row]=av1.y;
            As[nxt][a_k+6][a_row]=av1.z; As[nxt][a_k+7][a_row]=av1.w;
            *(float4*)&Bs[nxt][b_k][b_n]     = bv0;
            *(float4*)&Bs[nxt][b_k][b_n + 4] = bv1;
        }
        __syncthreads();
    }

    #pragma unroll
    for (int half = 0; half < 2; half++) {
        #pragma unroll
        for (int i = 0; i < 4; i++) {
            const int r = row0 + half * 64 + ty * 4 + i;
            if (r < nrows) {
                const int ai = half * 4 + i;
                float2 c0 = unpack2(acc2[ai][0]);
                float2 c1 = unpack2(acc2[ai][1]);
                float2 c2 = unpack2(acc2[ai][2]);
                float2 c3 = unpack2(acc2[ai][3]);
                float4 o0 = make_float4(c0.x, c0.y, c1.x, c1.y);
                float4 o1 = make_float4(c2.x, c2.y, c3.x, c3.y);
                *(float4*)(C + (long)r * EMBD + col0 + tx * 4)      = o0;
                *(float4*)(C + (long)r * EMBD + col0 + 64 + tx * 4) = o1;
            }
        }
    }
}

// =================== Wc projection (+bias), 64x128 tiles ====================
#define WBM 64
__global__ void __launch_bounds__(256)
wc_kernel(const float* __restrict__ X, const float* __restrict__ W,
          const float* __restrict__ bias, float* __restrict__ C)
{
    __shared__ float As[2][BK][WBM + 4];
    __shared__ float Bs[2][BK][BN];

    const int tid  = threadIdx.x;
    const int row0 = blockIdx.y * WBM;
    const int col0 = blockIdx.x * BN;

    const int a_row = tid >> 2;
    const int a_k   = (tid & 3) * 4;
    const int b_k   = tid >> 4;
    const int b_n   = (tid & 15) * 8;
    const int tx = tid & 15;
    const int ty = tid >> 4;

    const float* xrow = X + (long)(row0 + a_row) * EMBD;
    const float* wptr = W + (long)b_k * EMBD + col0 + b_n;

    float4 av, bv0, bv1;
    av  = *(const float4*)(xrow + a_k);
    bv0 = *(const float4*)(wptr);
    bv1 = *(const float4*)(wptr + 4);
    As[0][a_k+0][a_row]=av.x; As[0][a_k+1][a_row]=av.y;
    As[0][a_k+2][a_row]=av.z; As[0][a_k+3][a_row]=av.w;
    *(float4*)&Bs[0][b_k][b_n]     = bv0;
    *(float4*)&Bs[0][b_k][b_n + 4] = bv1;
    __syncthreads();

    ull acc2[4][4] = {};

    #pragma unroll 1
    for (int ks = 0; ks < EMBD / BK; ks++) {
        const int cur = ks & 1;
        const bool has_next = (ks < EMBD / BK - 1);
        if (has_next) {
            const int k0 = (ks + 1) * BK;
            av  = *(const float4*)(xrow + k0 + a_k);
            bv0 = *(const float4*)(wptr + (long)k0 * EMBD);
            bv1 = *(const float4*)(wptr + (long)k0 * EMBD + 4);
        }
        #pragma unroll
        for (int kk = 0; kk < BK; kk++) {
            float4 a0 = *(const float4*)&As[cur][kk][ty * 4];
            ulonglong2 p0 = *(const ulonglong2*)&Bs[cur][kk][tx * 4];
            ulonglong2 p1 = *(const ulonglong2*)&Bs[cur][kk][64 + tx * 4];
            ull B2[4] = {p0.x, p0.y, p1.x, p1.y};
            float a[4] = {a0.x, a0.y, a0.z, a0.w};
            #pragma unroll
            for (int i = 0; i < 4; i++) {
                const ull ai = bcast2(a[i]);
                #pragma unroll
                for (int j = 0; j < 4; j++)
                    acc2[i][j] = fma2(ai, B2[j], acc2[i][j]);
            }
        }
        if (has_next) {
            const int nxt = 1 - cur;
            As[nxt][a_k+0][a_row]=av.x; As[nxt][a_k+1][a_row]=av.y;
            As[nxt][a_k+2][a_row]=av.z; As[nxt][a_k+3][a_row]=av.w;
            *(float4*)&Bs[nxt][b_k][b_n]     = bv0;
            *(float4*)&Bs[nxt][b_k][b_n + 4] = bv1;
        }
        __syncthreads();
    }

    float4 bb0 = *(const float4*)(bias + col0 + tx * 4);
    float4 bb1 = *(const float4*)(bias + col0 + 64 + tx * 4);

    #pragma unroll
    for (int i = 0; i < 4; i++) {
        const int r = row0 + ty * 4 + i;
        float2 c0 = unpack2(acc2[i][0]);
        float2 c1 = unpack2(acc2[i][1]);
        float2 c2 = unpack2(acc2[i][2]);
        float2 c3 = unpack2(acc2[i][3]);
        float4 o0 = make_float4(c0.x+bb0.x, c0.y+bb0.y, c1.x+bb0.z, c1.y+bb0.w);
        float4 o1 = make_float4(c2.x+bb1.x, c2.y+bb1.y, c3.x+bb1.z, c3.y+bb1.w);
        *(float4*)(C + (long)r * EMBD + col0 + tx * 4)      = o0;
        *(float4*)(C + (long)r * EMBD + col0 + 64 + tx * 4) = o1;
    }
}

// =================== attention: 2 queries/thread, 64-thread blocks =========
__global__ void __launch_bounds__(64)
attn_kernel(const float* __restrict__ Q, const float* __restrict__ K,
            const float* __restrict__ V, float* __restrict__ O)
{
    __shared__ float Ks[128][DHEAD];
    __shared__ float Vs[128][DHEAD];

    const int h = blockIdx.x;
    const int b = blockIdx.y;
    const int tid = threadIdx.x;      // 0..63
    const int ma = tid;
    const int mb = tid + 64;

    ull qa[8], qb[8];
    {
        const float* qpa = Q + ((long)b * MROWS + ma) * EMBD + h * DHEAD;
        const float* qpb = Q + ((long)b * MROWS + mb) * EMBD + h * DHEAD;
        #pragma unroll
        for (int p = 0; p < 4; p++) {
            ulonglong2 va = *(const ulonglong2*)(qpa + p * 4);
            ulonglong2 vb = *(const ulonglong2*)(qpb + p * 4);
            qa[2*p] = va.x; qa[2*p+1] = va.y;
            qb[2*p] = vb.x; qb[2*p+1] = vb.y;
        }
    }

    float la = 0.0f, lb = 0.0f;
    ull acca[8] = {}, accb[8] = {};

    #pragma unroll 1
    for (int c = 0; c < 4; c++) {
        const int t0 = c * 128;
        __syncthreads();
        #pragma unroll
        for (int j = 0; j < 8; j++) {
            const int idx = tid + j * 64;          // 0..511
            const int rr = idx >> 2, cc = (idx & 3) * 4;
            const long base = ((long)b * TTOK + t0 + rr) * EMBD + h * DHEAD + cc;
            *(float4*)&Ks[rr][cc] = *(const float4*)(K + base);
            *(float4*)&Vs[rr][cc] = *(const float4*)(V + base);
        }
        __syncthreads();

        #pragma unroll 1
        for (int tt = 0; tt < 128; tt += 4) {
            float sa[4], sb[4];
            #pragma unroll
            for (int j = 0; j < 4; j++) {
                const ulonglong2* kp = (const ulonglong2*)Ks[tt + j];
                ulonglong2 k0 = kp[0], k1 = kp[1], k2v = kp[2], k3 = kp[3];
                ull da = mul2(qa[0], k0.x);
                ull db = mul2(qb[0], k0.x);
                da = fma2(qa[1], k0.y, da);  db = fma2(qb[1], k0.y, db);
                da = fma2(qa[2], k1.x, da);  db = fma2(qb[2], k1.x, db);
                da = fma2(qa[3], k1.y, da);  db = fma2(qb[3], k1.y, db);
                da = fma2(qa[4], k2v.x, da); db = fma2(qb[4], k2v.x, db);
                da = fma2(qa[5], k2v.y, da); db = fma2(qb[5], k2v.y, db);
                da = fma2(qa[6], k3.x, da);  db = fma2(qb[6], k3.x, db);
                da = fma2(qa[7], k3.y, da);  db = fma2(qb[7], k3.y, db);
                float2 fa = unpack2(da), fb = unpack2(db);
                sa[j] = (fa.x + fa.y) * 0.25f;
                sb[j] = (fb.x + fb.y) * 0.25f;
            }
            float pa[4], pb[4];
            #pragma unroll
            for (int j = 0; j < 4; j++) {
                pa[j] = __expf(sa[j]); la += pa[j];
                pb[j] = __expf(sb[j]); lb += pb[j];
            }
            #pragma unroll
            for (int j = 0; j < 4; j++) {
                const ull pba = bcast2(pa[j]);
                const ull pbb = bcast2(pb[j]);
                const ulonglong2* vp = (const ulonglong2*)Vs[tt + j];
                ulonglong2 v0 = vp[0], v1 = vp[1];
                acca[0] = fma2(pba, v0.x, acca[0]); accb[0] = fma2(pbb, v0.x, accb[0]);
                acca[1] = fma2(pba, v0.y, acca[1]); accb[1] = fma2(pbb, v0.y, accb[1]);
                acca[2] = fma2(pba, v1.x, acca[2]); accb[2] = fma2(pbb, v1.x, accb[2]);
                acca[3] = fma2(pba, v1.y, acca[3]); accb[3] = fma2(pbb, v1.y, accb[3]);
                ulonglong2 v2v = vp[2], v3 = vp[3];
                acca[4] = fma2(pba, v2v.x, acca[4]); accb[4] = fma2(pbb, v2v.x, accb[4]);
                acca[5] = fma2(pba, v2v.y, acca[5]); accb[5] = fma2(pbb, v2v.y, accb[5]);
                acca[6] = fma2(pba, v3.x, acca[6]);  accb[6] = fma2(pbb, v3.x, accb[6]);
                acca[7] = fma2(pba, v3.y, acca[7]);  accb[7] = fma2(pbb, v3.y, accb[7]);
            }
        }
    }

    // tail token t = 512 (from global)
    {
        const long base = ((long)b * TTOK + 512) * EMBD + h * DHEAD;
        const ulonglong2* kp = (const ulonglong2*)(K + base);
        ulonglong2 k0 = kp[0], k1 = kp[1], k2v = kp[2], k3 = kp[3];
        ull da = mul2(qa[0], k0.x);
        ull db = mul2(qb[0], k0.x);
        da = fma2(qa[1], k0.y, da);  db = fma2(qb[1], k0.y, db);
        da = fma2(qa[2], k1.x, da);  db = fma2(qb[2], k1.x, db);
        da = fma2(qa[3], k1.y, da);  db = fma2(qb[3], k1.y, db);
        da = fma2(qa[4], k2v.x, da); db = fma2(qb[4], k2v.x, db);
        da = fma2(qa[5], k2v.y, da); db = fma2(qb[5], k2v.y, db);
        da = fma2(qa[6], k3.x, da);  db = fma2(qb[6], k3.x, db);
        da = fma2(qa[7], k3.y, da);  db = fma2(qb[7], k3.y, db);
        float2 fa = unpack2(da), fb = unpack2(db);
        const float pa = __expf((fa.x + fa.y) * 0.25f);
        const float pb = __expf((fb.x + fb.y) * 0.25f);
        la += pa; lb += pb;
        const ull pba = bcast2(pa);
        const ull pbb = bcast2(pb);
        const ulonglong2* vp = (const ulonglong2*)(V + base);
        ulonglong2 v0 = vp[0], v1 = vp[1], v2v = vp[2], v3 = vp[3];
        acca[0] = fma2(pba, v0.x,  acca[0]); accb[0] = fma2(pbb, v0.x,  accb[0]);
        acca[1] = fma2(pba, v0.y,  acca[1]); accb[1] = fma2(pbb, v0.y,  accb[1]);
        acca[2] = fma2(pba, v1.x,  acca[2]); accb[2] = fma2(pbb, v1.x,  accb[2]);
        acca[3] = fma2(pba, v1.y,  acca[3]); accb[3] = fma2(pbb, v1.y,  accb[3]);
        acca[4] = fma2(pba, v2v.x, acca[4]); accb[4] = fma2(pbb, v2v.x, accb[4]);
        acca[5] = fma2(pba, v2v.y, acca[5]); accb[5] = fma2(pbb, v2v.y, accb[5]);
        acca[6] = fma2(pba, v3.x,  acca[6]); accb[6] = fma2(pbb, v3.x,  accb[6]);
        acca[7] = fma2(pba, v3.y,  acca[7]); accb[7] = fma2(pbb, v3.y,  accb[7]);
    }

    const float inva = 1.0f / la;
    const float invb = 1.0f / lb;
    float* opa = O + ((long)b * MROWS + ma) * EMBD + h * DHEAD;
    float* opb = O + ((long)b * MROWS + mb) * EMBD + h * DHEAD;
    #pragma unroll
    for (int p = 0; p < 4; p++) {
        float2 x0 = unpack2(acca[2*p]);
        float2 x1 = unpack2(acca[2*p+1]);
        *(float4*)(opa + p * 4) = make_float4(x0.x*inva, x0.y*inva, x1.x*inva, x1.y*inva);
        float2 y0 = unpack2(accb[2*p]);
        float2 y1 = unpack2(accb[2*p+1]);
        *(float4*)(opb + p * 4) = make_float4(y0.x*invb, y0.y*invb, y1.x*invb, y1.y*invb);
    }
}

// =================== score2: 4 full col tiles, scalar epilogue =============
// NOTE: out/mask rows have stride 513 (odd) -> only 4-byte alignment is
// guaranteed at (m*513 + t); epilogue must use scalar accesses.
__global__ void __launch_bounds__(256, 2)
score2_kernel(const float* __restrict__ MH, const float* __restrict__ jobs,
              const float* __restrict__ skip, const float* __restrict__ mask,
              float* __restrict__ out, float* __restrict__ sums)
{
    __shared__ float As[2][BK][ASTRIDE];
    __shared__ float Bs[2][BK][BN + 4];
    __shared__ float red[256];

    const int tid  = threadIdx.x;
    const int b    = blockIdx.z;
    const int col0 = blockIdx.x * BN;   // 0,128,256,384 -> t <= 511 always

    const int a_row = tid >> 1;
    const int a_k   = (tid & 1) * 8;
    const int tx = tid & 15;
    const int ty = tid >> 4;

    const float* arow = MH + ((long)b * MROWS + a_row) * EMBD;

    const int t_l = tid >> 1;
    const float* brow = jobs_row(jobs, skip, b, col0 + t_l);

    float4 av0, av1, bv0, bv1;
    av0 = *(const float4*)(arow + a_k);
    av1 = *(const float4*)(arow + a_k + 4);
    bv0 = *(const float4*)(brow + a_k);
    bv1 = *(const float4*)(brow + a_k + 4);
    As[0][a_k+0][a_row]=av0.x; As[0][a_k+1][a_row]=av0.y;
    As[0][a_k+2][a_row]=av0.z; As[0][a_k+3][a_row]=av0.w;
    As[0][a_k+4][a_row]=av1.x; As[0][a_k+5][a_row]=av1.y;
    As[0][a_k+6][a_row]=av1.z; As[0][a_k+7][a_row]=av1.w;
    Bs[0][a_k+0][t_l]=bv0.x; Bs[0][a_k+1][t_l]=bv0.y;
    Bs[0][a_k+2][t_l]=bv0.z; Bs[0][a_k+3][t_l]=bv0.w;
    Bs[0][a_k+4][t_l]=bv1.x; Bs[0][a_k+5][t_l]=bv1.y;
    Bs[0][a_k+6][t_l]=bv1.z; Bs[0][a_k+7][t_l]=bv1.w;
    __syncthreads();

    ull acc2[8][4] = {};

    #pragma unroll 1
    for (int ks = 0; ks < EMBD / BK; ks++) {
        const int cur = ks & 1;
        const bool has_next = (ks < EMBD / BK - 1);
        if (has_next) {
            const int k0 = (ks + 1) * BK;
            av0 = *(const float4*)(arow + k0 + a_k);
            av1 = *(const float4*)(arow + k0 + a_k + 4);
            bv0 = *(const float4*)(brow + k0 + a_k);
            bv1 = *(const float4*)(brow + k0 + a_k + 4);
        }
        GEMM_MICRO(cur)
        if (has_next) {
            const int nxt = 1 - cur;
            As[nxt][a_k+0][a_row]=av0.x; As[nxt][a_k+1][a_row]=av0.y;
            As[nxt][a_k+2][a_row]=av0.z; As[nxt][a_k+3][a_row]=av0.w;
            As[nxt][a_k+4][a_row]=av1.x; As[nxt][a_k+5][a_row]=av1.y;
            As[nxt][a_k+6][a_row]=av1.z; As[nxt][a_k+7][a_row]=av1.w;
            Bs[nxt][a_k+0][t_l]=bv0.x; Bs[nxt][a_k+1][t_l]=bv0.y;
            Bs[nxt][a_k+2][t_l]=bv0.z; Bs[nxt][a_k+3][t_l]=bv0.w;
            Bs[nxt][a_k+4][t_l]=bv1.x; Bs[nxt][a_k+5][t_l]=bv1.y;
            Bs[nxt][a_k+6][t_l]=bv1.z; Bs[nxt][a_k+7][t_l]=bv1.w;
        }
        __syncthreads();
    }

    float lsum = 0.0f;
    #pragma unroll
    for (int half = 0; half < 2; half++) {
        #pragma unroll
        for (int i = 0; i < 4; i++) {
            const int m = half * 64 + ty * 4 + i;
            const int ai = half * 4 + i;
            const long rowbase = (long)b * OUT_PER_B + (long)m * TTOK;
            #pragma unroll
            for (int jh = 0; jh < 2; jh++) {
                const int t = col0 + jh * 64 + tx * 4;
                float2 v0 = unpack2(acc2[ai][jh * 2 + 0]);
                float2 v1 = unpack2(acc2[ai][jh * 2 + 1]);
                float vv[4] = {v0.x, v0.y, v1.x, v1.y};
                #pragma unroll
                for (int e = 0; e < 4; e++) {
                    const long li = rowbase + t + e;
                    const float y = __expf(10.0f * tanh_fast(vv[e] * 0.0625f) + mask[li]);
                    out[li] = y;
                    lsum += y;
                }
            }
        }
    }

    red[tid] = lsum;
    __syncthreads();
    #pragma unroll
    for (int s = 128; s > 0; s >>= 1) {
        if (tid < s) red[tid] += red[tid + s];
        __syncthreads();
    }
    if (tid == 0) atomicAdd(&sums[b], red[0]);
}

// =================== t=512 column tail: 64 blocks x 128 thr ================
__global__ void __launch_bounds__(128)
tail_kernel(const float* __restrict__ MH, const float* __restrict__ jobs,
            const float* __restrict__ mask, float* __restrict__ out,
            float* __restrict__ sums)
{
    __shared__ float jrow[EMBD];
    __shared__ float red[128];

    const int b = blockIdx.x;
    const int m = threadIdx.x;

    // jobs_virtual[b][512] = jobs[b][511]
    const float* jr = jobs + ((long)b * JJOBS + 511) * EMBD;
    *(float2*)&jrow[m * 2] = *(const float2*)(jr + m * 2);
    __syncthreads();

    const float* mh = MH + ((long)b * MROWS + m) * EMBD;
    ull d2 = bcast2(0.0f);
    #pragma unroll
    for (int k = 0; k < EMBD; k += 8) {
        ulonglong2 a = *(const ulonglong2*)(mh + k);
        ulonglong2 a2 = *(const ulonglong2*)(mh + k + 4);
        ulonglong2 w = *(const ulonglong2*)&jrow[k];
        ulonglong2 w2 = *(const ulonglong2*)&jrow[k + 4];
        d2 = fma2(a.x, w.x, d2);
        d2 = fma2(a.y, w.y, d2);
        d2 = fma2(a2.x, w2.x, d2);
        d2 = fma2(a2.y, w2.y, d2);
    }
    float2 f = unpack2(d2);
    const float sc = (f.x + f.y) * 0.0625f;
    const long li = (long)b * OUT_PER_B + (long)m * TTOK + 512;
    const float y = __expf(10.0f * tanh_fast(sc) + mask[li]);
    out[li] = y;

    red[m] = y;
    __syncthreads();
    #pragma unroll
    for (int s = 64; s > 0; s >>= 1) {
        if (m < s) red[m] += red[m + s];
        __syncthreads();
    }
    if (m == 0) atomicAdd(&sums[b], red[0]);
}

// =================== normalize =======================
__global__ void __launch_bounds__(256)
norm_kernel(float4* __restrict__ out, const float* __restrict__ sums)
{
    const int b = blockIdx.y;
    const long per_b4 = OUT_PER_B / 4;
    const long idx = (long)blockIdx.x * blockDim.x + threadIdx.x;
    if (idx < per_b4) {
        const float inv = 1.0f / sums[b];
        float4 v = out[(long)b * per_b4 + idx];
        v.x *= inv; v.y *= inv; v.z *= inv; v.w *= inv;
        out[(long)b * per_b4 + idx] = v;
    }
}

// =================== launch ===================
extern "C" void kernel_launch(void* const* d_in, const int* in_sizes, int n_in,
                              void* d_out, int out_size)
{
    const float* machine = (const float*)d_in[0];
    const float* jobs    = (const float*)d_in[1];
    const float* mask    = (const float*)d_in[2];
    const float* Wq3     = (const float*)d_in[3];
    const float* Wk      = (const float*)d_in[4];
    const float* Wv      = (const float*)d_in[5];
    const float* Wc      = (const float*)d_in[6];
    const float* bc      = (const float*)d_in[7];
    const float* skip    = (const float*)d_in[8];
    float* out = (float*)d_out;

    float *Qp, *Kp, *Vp, *Op, *MHp, *Sp;
    cudaGetSymbolAddress((void**)&Qp,  g_Q);
    cudaGetSymbolAddress((void**)&Kp,  g_K);
    cudaGetSymbolAddress((void**)&Vp,  g_V);
    cudaGetSymbolAddress((void**)&Op,  g_O);
    cudaGetSymbolAddress((void**)&MHp, g_MH);
    cudaGetSymbolAddress((void**)&Sp,  g_SUM);

    const int kv_tiles = (BATCH * TTOK + BM - 1) / BM;   // 257
    proj_kernel<<<dim3(EMBD / BN, kv_tiles, 3), 256>>>(
        jobs, skip, machine, Wk, Wv, Wq3, Kp, Vp, Qp, Sp);

    attn_kernel<<<dim3(HEADS, BATCH), 64>>>(Qp, Kp, Vp, Op);

    wc_kernel<<<dim3(EMBD / BN, (BATCH * MROWS) / WBM), 256>>>(Op, Wc, bc, MHp);

    score2_kernel<<<dim3(4, 1, BATCH), 256>>>(MHp, jobs, skip, mask, out, Sp);
    tail_kernel<<<BATCH, 128>>>(MHp, jobs, mask, out, Sp);

    const int per_b4 = OUT_PER_B / 4;
    norm_kernel<<<dim3((per_b4 + 255) / 256, BATCH), 256>>>((float4*)out, Sp);
}